// round 12
// baseline (speedup 1.0000x reference)
#include <cuda_runtime.h>
#include <cuda_bf16.h>
#include <cstdint>

#define NSMP   8192
#define NA     512
#define DOUT   256
#define PITCH  8712   // input row length
#define ACOL0  512    // A starts at input col 512
#define OPITCH 8448   // output row length

// Scratch (static device globals — no runtime allocation)
__device__ float g_part[64 * NSMP];
__device__ float g_dinv[NSMP];
__device__ __align__(16) __nv_bfloat16 g_supT[(size_t)DOUT * NSMP]; // S_T[n][j]
__device__ __align__(16) __nv_bfloat16 g_WT[(size_t)DOUT * NA];     // W^T[n][k] bf16
__device__ __align__(16) __nv_bfloat16 g_Ab[(size_t)NSMP * NSMP];   // bf16(A+I)

// ---------------------------------------------------------------------------
// PTX helpers (base-target-safe)
// ---------------------------------------------------------------------------
__device__ __forceinline__ uint32_t s2u(const void* p) {
    return (uint32_t)__cvta_generic_to_shared(p);
}
__device__ __forceinline__ void cp_async16(uint32_t s, const void* g) {
    asm volatile("cp.async.cg.shared.global [%0], [%1], 16;" :: "r"(s), "l"(g) : "memory");
}
__device__ __forceinline__ void cp_commit() {
    asm volatile("cp.async.commit_group;" ::: "memory");
}
template <int N>
__device__ __forceinline__ void cp_wait() {
    asm volatile("cp.async.wait_group %0;" :: "n"(N) : "memory");
}
__device__ __forceinline__ void ldsm4(uint32_t* r, uint32_t addr) {
    asm volatile("ldmatrix.sync.aligned.m8n8.x4.shared.b16 {%0,%1,%2,%3}, [%4];"
                 : "=r"(r[0]), "=r"(r[1]), "=r"(r[2]), "=r"(r[3]) : "r"(addr));
}
__device__ __forceinline__ void mma16816(float* d, const uint32_t* a, uint32_t b0, uint32_t b1) {
    asm volatile(
        "mma.sync.aligned.m16n8k16.row.col.f32.bf16.bf16.f32 "
        "{%0,%1,%2,%3}, {%4,%5,%6,%7}, {%8,%9}, {%0,%1,%2,%3};"
        : "+f"(d[0]), "+f"(d[1]), "+f"(d[2]), "+f"(d[3])
        : "r"(a[0]), "r"(a[1]), "r"(a[2]), "r"(a[3]), "r"(b0), "r"(b1));
}
// SW128-swizzled smem offset for (row, 16B-chunk c) with 128B rows
__device__ __forceinline__ uint32_t swz(int row, int c) {
    return (uint32_t)(row * 128 + ((c ^ (row & 7)) << 4));
}

// ---------------------------------------------------------------------------
// Kernel: W^T bf16 (tiny, independent)
// ---------------------------------------------------------------------------
__global__ void wt_kernel(const float* __restrict__ w) {
    __shared__ float ts[32][33];
    int k0 = blockIdx.x * 32, n0 = blockIdx.y * 32;
    int t = threadIdx.x;
    int a = t >> 5, b = t & 31;
    #pragma unroll
    for (int i = 0; i < 4; ++i)
        ts[a + 8 * i][b] = w[(size_t)(k0 + a + 8 * i) * DOUT + n0 + b];
    __syncthreads();
    #pragma unroll
    for (int i = 0; i < 4; ++i)
        g_WT[(size_t)(n0 + a + 8 * i) * NA + k0 + b] = __float2bfloat16(ts[b][a + 8 * i]);
}

// ---------------------------------------------------------------------------
// fused_pre: blocks 0..127  -> support role (unscaled S_T = bf16(X@W))
//            blocks 128..639 -> colsum role (partials + A+I fp32 + bf16 A)
// ---------------------------------------------------------------------------
#define SP_A0 0
#define SP_B0 8192
#define SP_A1 40960
#define SP_B1 49152
#define SP_TOTAL 81920
#define ST_PITCH 144

__device__ __forceinline__ void sp_load(const float* in, char* smem, int buf, int k0,
                                        int tid, int m0) {
    uint32_t bs = s2u(smem + (buf ? SP_B1 : SP_B0));
    const char* gB = (const char*)g_WT + (size_t)k0 * 2;
    #pragma unroll
    for (int c = 0; c < 8; ++c) {
        int chunk = tid + c * 256;
        int row = chunk >> 3;
        int seg = chunk & 7;
        cp_async16(bs + swz(row, seg), gB + (size_t)row * (NA * 2) + seg * 16);
    }
    cp_commit();
    char* As = smem + (buf ? SP_A1 : SP_A0);
    int f = tid & 15, r0 = tid >> 4;
    #pragma unroll
    for (int i = 0; i < 4; ++i) {
        int row = r0 + 16 * i;
        float4 v = *(const float4*)(in + (size_t)(m0 + row) * PITCH + k0 + f * 4);
        __nv_bfloat162 h0 = __floats2bfloat162_rn(v.x, v.y);
        __nv_bfloat162 h1 = __floats2bfloat162_rn(v.z, v.w);
        *(uint2*)(As + swz(row, f >> 1) + (f & 1) * 8) =
            make_uint2(*(uint32_t*)&h0, *(uint32_t*)&h1);
    }
}

__device__ void support_role(const float* __restrict__ in, char* smem, int bid) {
    int tid = threadIdx.x;
    int wid = tid >> 5, lane = tid & 31;
    int m0 = bid * 64;
    int warp_m = (wid & 1) * 32;
    int warp_n = (wid >> 1) * 64;

    int rowA[2], rowB[4];
    #pragma unroll
    for (int mi = 0; mi < 2; ++mi) rowA[mi] = warp_m + mi * 16 + (lane & 15);
    int hiA = lane >> 4;
    #pragma unroll
    for (int nb = 0; nb < 4; ++nb)
        rowB[nb] = warp_n + nb * 16 + ((lane >> 4) << 3) + (lane & 7);
    int hiB = (lane >> 3) & 1;

    float acc[2][8][4] = {};

    sp_load(in, smem, 0, 0, tid, m0);
    for (int it = 0; it < NA / 64; ++it) {
        int buf = it & 1;
        if (it + 1 < NA / 64) { sp_load(in, smem, buf ^ 1, (it + 1) * 64, tid, m0); cp_wait<1>(); }
        else cp_wait<0>();
        __syncthreads();
        uint32_t As = s2u(smem + (buf ? SP_A1 : SP_A0));
        uint32_t Bs = s2u(smem + (buf ? SP_B1 : SP_B0));
        #pragma unroll
        for (int kk = 0; kk < 4; ++kk) {
            uint32_t a[2][4];
            #pragma unroll
            for (int mi = 0; mi < 2; ++mi)
                ldsm4(a[mi], As + swz(rowA[mi], kk * 2 + hiA));
            #pragma unroll
            for (int nb = 0; nb < 4; ++nb) {
                uint32_t b[4];
                ldsm4(b, Bs + swz(rowB[nb], kk * 2 + hiB));
                mma16816(acc[0][2 * nb],     a[0], b[0], b[1]);
                mma16816(acc[0][2 * nb + 1], a[0], b[2], b[3]);
                mma16816(acc[1][2 * nb],     a[1], b[0], b[1]);
                mma16816(acc[1][2 * nb + 1], a[1], b[2], b[3]);
            }
        }
        __syncthreads();
    }

    // epilogue: UNSCALED bf16, stage transposed [n][j], STG coalesced
    int qr = lane >> 2, qc = (lane & 3) * 2;
    #pragma unroll
    for (int mi = 0; mi < 2; ++mi) {
        int j0 = warp_m + mi * 16 + qr;
        #pragma unroll
        for (int n8 = 0; n8 < 8; ++n8) {
            int n = warp_n + n8 * 8 + qc;
            *(__nv_bfloat16*)(smem + n * ST_PITCH + j0 * 2)             = __float2bfloat16(acc[mi][n8][0]);
            *(__nv_bfloat16*)(smem + (n + 1) * ST_PITCH + j0 * 2)       = __float2bfloat16(acc[mi][n8][1]);
            *(__nv_bfloat16*)(smem + n * ST_PITCH + (j0 + 8) * 2)       = __float2bfloat16(acc[mi][n8][2]);
            *(__nv_bfloat16*)(smem + (n + 1) * ST_PITCH + (j0 + 8) * 2) = __float2bfloat16(acc[mi][n8][3]);
        }
    }
    __syncthreads();
    #pragma unroll
    for (int c = 0; c < 8; ++c) {
        int chunk = tid + c * 256;
        int n = chunk >> 3;
        int seg = chunk & 7;
        uint4 v = *(const uint4*)(smem + n * ST_PITCH + seg * 16);
        *(uint4*)((char*)g_supT + ((size_t)n * NSMP + m0) * 2 + seg * 16) = v;
    }
}

__device__ void colsum_role(const float* __restrict__ in, float* __restrict__ out, int b) {
    int bx = b & 7, by = b >> 3;
    int col = (bx * 256 + threadIdx.x) * 4;
    int r0  = by * 128;
    const float* p = in + (size_t)r0 * PITCH + ACOL0 + col;
    float*       q = out + (size_t)r0 * OPITCH + DOUT + col;
    __nv_bfloat16* ab = g_Ab + (size_t)r0 * NSMP + col;
    float4 s = make_float4(0.f, 0.f, 0.f, 0.f);
    #pragma unroll 8
    for (int r = 0; r < 128; ++r) {
        float4 v = *(const float4*)p;
        s.x += v.x; s.y += v.y; s.z += v.z; s.w += v.w;   // raw A sums (pre-identity)
        int d = (r0 + r) - col;
        if ((unsigned)d < 4u) ((float*)&v)[d] += 1.f;     // +I
        __stcs((float4*)q, v);                            // fp32 A+I -> out[:,256:]
        __nv_bfloat162 h0 = __floats2bfloat162_rn(v.x, v.y);
        __nv_bfloat162 h1 = __floats2bfloat162_rn(v.z, v.w);
        __stcs((uint2*)ab, make_uint2(*(uint32_t*)&h0, *(uint32_t*)&h1));
        p += PITCH; q += OPITCH; ab += NSMP;
    }
    *(float4*)(g_part + by * NSMP + col) = s;
}

__global__ void __launch_bounds__(256, 1) fused_pre(const float* __restrict__ in,
                                                    float* __restrict__ out) {
    extern __shared__ char smem[];
    if (blockIdx.x < 128) support_role(in, smem, blockIdx.x);
    else                  colsum_role(in, out, blockIdx.x - 128);
}

// ---------------------------------------------------------------------------
// finalize_scale: dinv for a 256-col slice + rescale g_supT[:, slice] by dinv
// ---------------------------------------------------------------------------
__global__ void finalize_scale() {
    __shared__ float sdv[256];
    int x = blockIdx.x;                 // 32 blocks
    int col = x * 256 + threadIdx.x;
    float s = 1.0f;
    #pragma unroll
    for (int i = 0; i < 64; ++i) s += g_part[i * NSMP + col];
    float dv = rsqrtf(s);
    g_dinv[col] = dv;
    sdv[threadIdx.x] = dv;
    __syncthreads();

    int tc = threadIdx.x & 31;          // 32 col-groups of 8 cols (16B)
    int tr = threadIdx.x >> 5;          // 8 row walkers
    int j0 = tc * 8;
    float d[8];
    #pragma unroll
    for (int i = 0; i < 8; ++i) d[i] = sdv[j0 + i];
    for (int r = tr; r < DOUT; r += 8) {
        uint4* p = (uint4*)(g_supT + (size_t)r * NSMP + x * 256 + j0);
        uint4 v = *p;
        uint32_t* vw = (uint32_t*)&v;
        #pragma unroll
        for (int h = 0; h < 4; ++h) {
            float2 f = __bfloat1622float2(*(__nv_bfloat162*)&vw[h]);
            f.x *= d[h * 2];
            f.y *= d[h * 2 + 1];
            __nv_bfloat162 r2 = __floats2bfloat162_rn(f.x, f.y);
            vw[h] = *(uint32_t*)&r2;
        }
        *p = v;
    }
}

// ---------------------------------------------------------------------------
// main (pure bf16 GEMM): out[:, :256] = diag(dinv) * bf16(A+I) @ S
// 128-thread CTAs (4 warps, warp tile 32x64), CTA 64x128, grid (128, 2),
// 3-stage cp.async ring (72KB smem). (unchanged from R11 — the winner)
// ---------------------------------------------------------------------------
#define MG7_STRIDE 24576   // per-stage: B(16KB) + A(8KB)
#define MG7_AOFF   16384
#define MG7_TOTAL  73728   // 3 stages
#define NIT        (NSMP / 64)

__device__ __forceinline__ void mg7_load(char* smem, int stage, int k0, int tid,
                                         int m0, int n0) {
    uint32_t bs = s2u(smem + stage * MG7_STRIDE);
    const char* gB = (const char*)g_supT + (size_t)n0 * (NSMP * 2) + (size_t)k0 * 2;
    #pragma unroll
    for (int c = 0; c < 8; ++c) {
        int chunk = tid + c * 128;
        int row = chunk >> 3;
        int seg = chunk & 7;
        cp_async16(bs + swz(row, seg), gB + (size_t)row * (NSMP * 2) + seg * 16);
    }
    uint32_t as_ = s2u(smem + stage * MG7_STRIDE + MG7_AOFF);
    const char* gA = (const char*)g_Ab + (size_t)m0 * (NSMP * 2) + (size_t)k0 * 2;
    #pragma unroll
    for (int c = 0; c < 4; ++c) {
        int chunk = tid + c * 128;
        int row = chunk >> 3;
        int seg = chunk & 7;
        cp_async16(as_ + swz(row, seg), gA + (size_t)row * (NSMP * 2) + seg * 16);
    }
    cp_commit();
}

__global__ void __launch_bounds__(128, 3) main_gemm7(float* __restrict__ out) {
    extern __shared__ char smem[];
    int tid = threadIdx.x;
    int wid = tid >> 5, lane = tid & 31;
    int m0 = blockIdx.x * 64;
    int n0 = blockIdx.y * 128;
    int warp_m = (wid & 1) * 32;
    int warp_n = (wid >> 1) * 64;

    int rowA[2], rowB[4];
    #pragma unroll
    for (int mi = 0; mi < 2; ++mi) rowA[mi] = warp_m + mi * 16 + (lane & 15);
    int hiA = lane >> 4;
    #pragma unroll
    for (int nb = 0; nb < 4; ++nb)
        rowB[nb] = warp_n + nb * 16 + ((lane >> 4) << 3) + (lane & 7);
    int hiB = (lane >> 3) & 1;

    float acc[2][8][4] = {};

    mg7_load(smem, 0, 0, tid, m0, n0);
    mg7_load(smem, 1, 64, tid, m0, n0);

    for (int it = 0; it < NIT; ++it) {
        int stage = it % 3;
        if (it + 1 < NIT) cp_wait<1>(); else cp_wait<0>();
        __syncthreads();
        if (it + 2 < NIT) mg7_load(smem, (it + 2) % 3, (it + 2) * 64, tid, m0, n0);

        uint32_t Af = s2u(smem + stage * MG7_STRIDE + MG7_AOFF);
        uint32_t Bs = s2u(smem + stage * MG7_STRIDE);
        #pragma unroll
        for (int kk = 0; kk < 4; ++kk) {
            uint32_t a[2][4];
            #pragma unroll
            for (int mi = 0; mi < 2; ++mi)
                ldsm4(a[mi], Af + swz(rowA[mi], kk * 2 + hiA));
            #pragma unroll
            for (int nb = 0; nb < 4; ++nb) {
                uint32_t b[4];
                ldsm4(b, Bs + swz(rowB[nb], kk * 2 + hiB));
                mma16816(acc[0][2 * nb],     a[0], b[0], b[1]);
                mma16816(acc[0][2 * nb + 1], a[0], b[2], b[3]);
                mma16816(acc[1][2 * nb],     a[1], b[0], b[1]);
                mma16816(acc[1][2 * nb + 1], a[1], b[2], b[3]);
            }
        }
    }

    // epilogue: scale by dinv[row], store out[:, n0 + warp_n ...]
    int qr = lane >> 2, qc = (lane & 3) * 2;
    #pragma unroll
    for (int mi = 0; mi < 2; ++mi) {
        int r0g = m0 + warp_m + mi * 16 + qr;
        float dv0 = g_dinv[r0g];
        float dv1 = g_dinv[r0g + 8];
        float* o0 = out + (size_t)r0g * OPITCH + n0;
        float* o1 = o0 + (size_t)8 * OPITCH;
        #pragma unroll
        for (int n8 = 0; n8 < 8; ++n8) {
            int col = warp_n + n8 * 8 + qc;
            o0[col]     = dv0 * acc[mi][n8][0];
            o0[col + 1] = dv0 * acc[mi][n8][1];
            o1[col]     = dv1 * acc[mi][n8][2];
            o1[col + 1] = dv1 * acc[mi][n8][3];
        }
    }
}

// ---------------------------------------------------------------------------
extern "C" void kernel_launch(void* const* d_in, const int* in_sizes, int n_in,
                              void* d_out, int out_size) {
    const float* in = (const float*)d_in[0];
    const float* w  = (const float*)d_in[1];
    float* out = (float*)d_out;

    cudaFuncSetAttribute(fused_pre,  cudaFuncAttributeMaxDynamicSharedMemorySize, SP_TOTAL);
    cudaFuncSetAttribute(main_gemm7, cudaFuncAttributeMaxDynamicSharedMemorySize, MG7_TOTAL);

    wt_kernel     <<<dim3(16, 8), 256>>>(w);
    fused_pre     <<<640, 256, SP_TOTAL>>>(in, out);
    finalize_scale<<<32, 256>>>();
    main_gemm7    <<<dim3(128, 2), 128, MG7_TOTAL>>>(out);
}

// round 13
// speedup vs baseline: 1.1302x; 1.1302x over previous
#include <cuda_runtime.h>
#include <cuda_bf16.h>
#include <cstdint>

#define NSMP   8192
#define NA     512
#define DOUT   256
#define PITCH  8712   // input row length
#define ACOL0  512    // A starts at input col 512
#define OPITCH 8448   // output row length

// Scratch (static device globals — no runtime allocation)
__device__ float g_part[64 * NSMP];
__device__ float g_dinv[NSMP];
__device__ __align__(16) __nv_bfloat16 g_supT[(size_t)DOUT * NSMP]; // S_T[n][j]
__device__ __align__(16) __nv_bfloat16 g_WT[(size_t)DOUT * NA];     // W^T[n][k] bf16
__device__ __align__(16) __nv_bfloat16 g_Ab[(size_t)NSMP * NSMP];   // bf16(A+I)

// ---------------------------------------------------------------------------
// PTX helpers (base-target-safe)
// ---------------------------------------------------------------------------
__device__ __forceinline__ uint32_t s2u(const void* p) {
    return (uint32_t)__cvta_generic_to_shared(p);
}
__device__ __forceinline__ void cp_async16(uint32_t s, const void* g) {
    asm volatile("cp.async.cg.shared.global [%0], [%1], 16;" :: "r"(s), "l"(g) : "memory");
}
__device__ __forceinline__ void cp_commit() {
    asm volatile("cp.async.commit_group;" ::: "memory");
}
template <int N>
__device__ __forceinline__ void cp_wait() {
    asm volatile("cp.async.wait_group %0;" :: "n"(N) : "memory");
}
__device__ __forceinline__ void ldsm4(uint32_t* r, uint32_t addr) {
    asm volatile("ldmatrix.sync.aligned.m8n8.x4.shared.b16 {%0,%1,%2,%3}, [%4];"
                 : "=r"(r[0]), "=r"(r[1]), "=r"(r[2]), "=r"(r[3]) : "r"(addr));
}
__device__ __forceinline__ void mma16816(float* d, const uint32_t* a, uint32_t b0, uint32_t b1) {
    asm volatile(
        "mma.sync.aligned.m16n8k16.row.col.f32.bf16.bf16.f32 "
        "{%0,%1,%2,%3}, {%4,%5,%6,%7}, {%8,%9}, {%0,%1,%2,%3};"
        : "+f"(d[0]), "+f"(d[1]), "+f"(d[2]), "+f"(d[3])
        : "r"(a[0]), "r"(a[1]), "r"(a[2]), "r"(a[3]), "r"(b0), "r"(b1));
}
// SW128-swizzled smem offset for (row, 16B-chunk c) with 128B rows
__device__ __forceinline__ uint32_t swz(int row, int c) {
    return (uint32_t)(row * 128 + ((c ^ (row & 7)) << 4));
}

// ---------------------------------------------------------------------------
// Kernel: W^T bf16 (tiny, independent)
// ---------------------------------------------------------------------------
__global__ void wt_kernel(const float* __restrict__ w) {
    __shared__ float ts[32][33];
    int k0 = blockIdx.x * 32, n0 = blockIdx.y * 32;
    int t = threadIdx.x;
    int a = t >> 5, b = t & 31;
    #pragma unroll
    for (int i = 0; i < 4; ++i)
        ts[a + 8 * i][b] = w[(size_t)(k0 + a + 8 * i) * DOUT + n0 + b];
    __syncthreads();
    #pragma unroll
    for (int i = 0; i < 4; ++i)
        g_WT[(size_t)(n0 + a + 8 * i) * NA + k0 + b] = __float2bfloat16(ts[b][a + 8 * i]);
}

// ---------------------------------------------------------------------------
// Kernel: colsum partials + A+I copy-out (fp32) + bf16(A+I) production.
// ---------------------------------------------------------------------------
__global__ void colsum_fused(const float* __restrict__ in, float* __restrict__ out) {
    int col = (blockIdx.x * 256 + threadIdx.x) * 4;
    int r0  = blockIdx.y * 128;
    const float* p = in + (size_t)r0 * PITCH + ACOL0 + col;
    float*       q = out + (size_t)r0 * OPITCH + DOUT + col;
    __nv_bfloat16* ab = g_Ab + (size_t)r0 * NSMP + col;
    float4 s = make_float4(0.f, 0.f, 0.f, 0.f);
    #pragma unroll 4
    for (int r = 0; r < 128; ++r) {
        float4 v = *(const float4*)p;
        s.x += v.x; s.y += v.y; s.z += v.z; s.w += v.w;   // raw A sums (pre-identity)
        int d = (r0 + r) - col;
        if ((unsigned)d < 4u) ((float*)&v)[d] += 1.f;     // +I
        __stcs((float4*)q, v);                            // fp32 A+I -> out[:,256:]
        __nv_bfloat162 h0 = __floats2bfloat162_rn(v.x, v.y);
        __nv_bfloat162 h1 = __floats2bfloat162_rn(v.z, v.w);
        __stcs((uint2*)ab, make_uint2(*(uint32_t*)&h0, *(uint32_t*)&h1));
        p += PITCH; q += OPITCH; ab += NSMP;
    }
    *(float4*)(g_part + blockIdx.y * NSMP + col) = s;
}

__global__ void finalize_d() {
    int col = blockIdx.x * 256 + threadIdx.x;
    float s = 1.0f;
    #pragma unroll
    for (int i = 0; i < 64; ++i) s += g_part[i * NSMP + col];
    g_dinv[col] = rsqrtf(s);
}

// ---------------------------------------------------------------------------
// support (mma.sync): S_T[n][j] = bf16( dinv[j] * (X @ W)[j,n] )  (R11 form)
// ---------------------------------------------------------------------------
#define SP_A0 0
#define SP_B0 8192
#define SP_A1 40960
#define SP_B1 49152
#define SP_TOTAL 81920
#define ST_PITCH 144

__device__ __forceinline__ void sp_load(const float* in, char* smem, int buf, int k0,
                                        int tid, int m0) {
    uint32_t bs = s2u(smem + (buf ? SP_B1 : SP_B0));
    const char* gB = (const char*)g_WT + (size_t)k0 * 2;
    #pragma unroll
    for (int c = 0; c < 8; ++c) {
        int chunk = tid + c * 256;
        int row = chunk >> 3;
        int seg = chunk & 7;
        cp_async16(bs + swz(row, seg), gB + (size_t)row * (NA * 2) + seg * 16);
    }
    cp_commit();
    char* As = smem + (buf ? SP_A1 : SP_A0);
    int f = tid & 15, r0 = tid >> 4;
    #pragma unroll
    for (int i = 0; i < 4; ++i) {
        int row = r0 + 16 * i;
        float4 v = *(const float4*)(in + (size_t)(m0 + row) * PITCH + k0 + f * 4);
        __nv_bfloat162 h0 = __floats2bfloat162_rn(v.x, v.y);
        __nv_bfloat162 h1 = __floats2bfloat162_rn(v.z, v.w);
        *(uint2*)(As + swz(row, f >> 1) + (f & 1) * 8) =
            make_uint2(*(uint32_t*)&h0, *(uint32_t*)&h1);
    }
}

__global__ void __launch_bounds__(256, 1) support_mma(const float* __restrict__ in) {
    extern __shared__ char smem[];
    int tid = threadIdx.x;
    int wid = tid >> 5, lane = tid & 31;
    int m0 = blockIdx.x * 64;
    int warp_m = (wid & 1) * 32;
    int warp_n = (wid >> 1) * 64;

    int rowA[2], rowB[4];
    #pragma unroll
    for (int mi = 0; mi < 2; ++mi) rowA[mi] = warp_m + mi * 16 + (lane & 15);
    int hiA = lane >> 4;
    #pragma unroll
    for (int nb = 0; nb < 4; ++nb)
        rowB[nb] = warp_n + nb * 16 + ((lane >> 4) << 3) + (lane & 7);
    int hiB = (lane >> 3) & 1;

    float acc[2][8][4] = {};

    sp_load(in, smem, 0, 0, tid, m0);
    for (int it = 0; it < NA / 64; ++it) {
        int buf = it & 1;
        if (it + 1 < NA / 64) { sp_load(in, smem, buf ^ 1, (it + 1) * 64, tid, m0); cp_wait<1>(); }
        else cp_wait<0>();
        __syncthreads();
        uint32_t As = s2u(smem + (buf ? SP_A1 : SP_A0));
        uint32_t Bs = s2u(smem + (buf ? SP_B1 : SP_B0));
        #pragma unroll
        for (int kk = 0; kk < 4; ++kk) {
            uint32_t a[2][4];
            #pragma unroll
            for (int mi = 0; mi < 2; ++mi)
                ldsm4(a[mi], As + swz(rowA[mi], kk * 2 + hiA));
            #pragma unroll
            for (int nb = 0; nb < 4; ++nb) {
                uint32_t b[4];
                ldsm4(b, Bs + swz(rowB[nb], kk * 2 + hiB));
                mma16816(acc[0][2 * nb],     a[0], b[0], b[1]);
                mma16816(acc[0][2 * nb + 1], a[0], b[2], b[3]);
                mma16816(acc[1][2 * nb],     a[1], b[0], b[1]);
                mma16816(acc[1][2 * nb + 1], a[1], b[2], b[3]);
            }
        }
        __syncthreads();
    }

    int qr = lane >> 2, qc = (lane & 3) * 2;
    #pragma unroll
    for (int mi = 0; mi < 2; ++mi) {
        int j0 = warp_m + mi * 16 + qr;
        float dv0 = g_dinv[m0 + j0];
        float dv1 = g_dinv[m0 + j0 + 8];
        #pragma unroll
        for (int n8 = 0; n8 < 8; ++n8) {
            int n = warp_n + n8 * 8 + qc;
            *(__nv_bfloat16*)(smem + n * ST_PITCH + j0 * 2)             = __float2bfloat16(dv0 * acc[mi][n8][0]);
            *(__nv_bfloat16*)(smem + (n + 1) * ST_PITCH + j0 * 2)       = __float2bfloat16(dv0 * acc[mi][n8][1]);
            *(__nv_bfloat16*)(smem + n * ST_PITCH + (j0 + 8) * 2)       = __float2bfloat16(dv1 * acc[mi][n8][2]);
            *(__nv_bfloat16*)(smem + (n + 1) * ST_PITCH + (j0 + 8) * 2) = __float2bfloat16(dv1 * acc[mi][n8][3]);
        }
    }
    __syncthreads();
    #pragma unroll
    for (int c = 0; c < 8; ++c) {
        int chunk = tid + c * 256;
        int n = chunk >> 3;
        int seg = chunk & 7;
        uint4 v = *(const uint4*)(smem + n * ST_PITCH + seg * 16);
        *(uint4*)((char*)g_supT + ((size_t)n * NSMP + m0) * 2 + seg * 16) = v;
    }
}

// ---------------------------------------------------------------------------
// main (pure bf16 GEMM): out[:, :256] = diag(dinv) * bf16(A+I) @ S
// CTA 64x64, grid (4, 128) n-fast (A L2 sharing), 4 warps (warp tile 32x32),
// 3-stage ring (48KB) -> 4 CTAs/SM. Fixes the 1.73 CTA/SM starvation of R11.
// ---------------------------------------------------------------------------
#define MG8_STRIDE 16384   // per-stage: B(8KB) + A(8KB)
#define MG8_AOFF   8192
#define MG8_TOTAL  49152   // 3 stages
#define NIT        (NSMP / 64)

__device__ __forceinline__ void mg8_load(char* smem, int stage, int k0, int tid,
                                         int m0, int n0) {
    // B tile: 64 x 64 bf16 (512 chunks, 4 per thread)
    uint32_t bs = s2u(smem + stage * MG8_STRIDE);
    const char* gB = (const char*)g_supT + (size_t)n0 * (NSMP * 2) + (size_t)k0 * 2;
    #pragma unroll
    for (int c = 0; c < 4; ++c) {
        int chunk = tid + c * 128;
        int row = chunk >> 3;
        int seg = chunk & 7;
        cp_async16(bs + swz(row, seg), gB + (size_t)row * (NSMP * 2) + seg * 16);
    }
    // A tile: 64 x 64 bf16 (512 chunks, 4 per thread)
    uint32_t as_ = s2u(smem + stage * MG8_STRIDE + MG8_AOFF);
    const char* gA = (const char*)g_Ab + (size_t)m0 * (NSMP * 2) + (size_t)k0 * 2;
    #pragma unroll
    for (int c = 0; c < 4; ++c) {
        int chunk = tid + c * 128;
        int row = chunk >> 3;
        int seg = chunk & 7;
        cp_async16(as_ + swz(row, seg), gA + (size_t)row * (NSMP * 2) + seg * 16);
    }
    cp_commit();
}

__global__ void __launch_bounds__(128, 4) main_gemm8(float* __restrict__ out) {
    extern __shared__ char smem[];
    int tid = threadIdx.x;
    int wid = tid >> 5, lane = tid & 31;
    int n0 = blockIdx.x * 64;    // n fast-varying: 4 consecutive CTAs share m0
    int m0 = blockIdx.y * 64;
    int warp_m = (wid & 1) * 32;
    int warp_n = (wid >> 1) * 32;

    int rowA[2], rowB[2];
    #pragma unroll
    for (int mi = 0; mi < 2; ++mi) rowA[mi] = warp_m + mi * 16 + (lane & 15);
    int hiA = lane >> 4;
    #pragma unroll
    for (int nb = 0; nb < 2; ++nb)
        rowB[nb] = warp_n + nb * 16 + ((lane >> 4) << 3) + (lane & 7);
    int hiB = (lane >> 3) & 1;

    float acc[2][4][4] = {};

    mg8_load(smem, 0, 0, tid, m0, n0);
    mg8_load(smem, 1, 64, tid, m0, n0);

    for (int it = 0; it < NIT; ++it) {
        int stage = it % 3;
        if (it + 1 < NIT) cp_wait<1>(); else cp_wait<0>();
        __syncthreads();
        if (it + 2 < NIT) mg8_load(smem, (it + 2) % 3, (it + 2) * 64, tid, m0, n0);

        uint32_t Bs = s2u(smem + stage * MG8_STRIDE);
        uint32_t Af = s2u(smem + stage * MG8_STRIDE + MG8_AOFF);
        #pragma unroll
        for (int kk = 0; kk < 4; ++kk) {
            uint32_t a[2][4];
            #pragma unroll
            for (int mi = 0; mi < 2; ++mi)
                ldsm4(a[mi], Af + swz(rowA[mi], kk * 2 + hiA));
            #pragma unroll
            for (int nb = 0; nb < 2; ++nb) {
                uint32_t b[4];
                ldsm4(b, Bs + swz(rowB[nb], kk * 2 + hiB));
                mma16816(acc[0][2 * nb],     a[0], b[0], b[1]);
                mma16816(acc[0][2 * nb + 1], a[0], b[2], b[3]);
                mma16816(acc[1][2 * nb],     a[1], b[0], b[1]);
                mma16816(acc[1][2 * nb + 1], a[1], b[2], b[3]);
            }
        }
    }

    // epilogue: scale by dinv[row], store out[:, n0 + warp_n ...]
    int qr = lane >> 2, qc = (lane & 3) * 2;
    #pragma unroll
    for (int mi = 0; mi < 2; ++mi) {
        int r0g = m0 + warp_m + mi * 16 + qr;
        float dv0 = g_dinv[r0g];
        float dv1 = g_dinv[r0g + 8];
        float* o0 = out + (size_t)r0g * OPITCH + n0;
        float* o1 = o0 + (size_t)8 * OPITCH;
        #pragma unroll
        for (int n8 = 0; n8 < 4; ++n8) {
            int col = warp_n + n8 * 8 + qc;
            o0[col]     = dv0 * acc[mi][n8][0];
            o0[col + 1] = dv0 * acc[mi][n8][1];
            o1[col]     = dv1 * acc[mi][n8][2];
            o1[col + 1] = dv1 * acc[mi][n8][3];
        }
    }
}

// ---------------------------------------------------------------------------
extern "C" void kernel_launch(void* const* d_in, const int* in_sizes, int n_in,
                              void* d_out, int out_size) {
    const float* in = (const float*)d_in[0];
    const float* w  = (const float*)d_in[1];
    float* out = (float*)d_out;

    cudaFuncSetAttribute(support_mma, cudaFuncAttributeMaxDynamicSharedMemorySize, SP_TOTAL);
    cudaFuncSetAttribute(main_gemm8,  cudaFuncAttributeMaxDynamicSharedMemorySize, MG8_TOTAL);

    wt_kernel   <<<dim3(16, 8), 256>>>(w);
    colsum_fused<<<dim3(8, 64), 256>>>(in, out);
    finalize_d  <<<32, 256>>>();
    support_mma <<<128, 256, SP_TOTAL>>>(in);
    main_gemm8  <<<dim3(4, 128), 128, MG8_TOTAL>>>(out);
}

// round 14
// speedup vs baseline: 1.1604x; 1.0267x over previous
#include <cuda_runtime.h>
#include <cuda_bf16.h>
#include <cstdint>

#define NSMP   8192
#define NA     512
#define DOUT   256
#define PITCH  8712   // input row length
#define ACOL0  512    // A starts at input col 512
#define OPITCH 8448   // output row length

// Scratch (static device globals — no runtime allocation)
__device__ float g_part[64 * NSMP];
__device__ float g_dinv[NSMP];
__device__ __align__(16) __nv_bfloat16 g_supT[(size_t)DOUT * NSMP]; // S_T[n][j]
__device__ __align__(16) __nv_bfloat16 g_WT[(size_t)DOUT * NA];     // W^T[n][k] bf16
__device__ __align__(16) __nv_bfloat16 g_Ab[(size_t)NSMP * NSMP];   // bf16(A+I)
__device__ __align__(16) float g_accP[4][(size_t)NSMP * DOUT];      // K-split partials

// ---------------------------------------------------------------------------
// PTX helpers (base-target-safe)
// ---------------------------------------------------------------------------
__device__ __forceinline__ uint32_t s2u(const void* p) {
    return (uint32_t)__cvta_generic_to_shared(p);
}
__device__ __forceinline__ void cp_async16(uint32_t s, const void* g) {
    asm volatile("cp.async.cg.shared.global [%0], [%1], 16;" :: "r"(s), "l"(g) : "memory");
}
__device__ __forceinline__ void cp_commit() {
    asm volatile("cp.async.commit_group;" ::: "memory");
}
template <int N>
__device__ __forceinline__ void cp_wait() {
    asm volatile("cp.async.wait_group %0;" :: "n"(N) : "memory");
}
__device__ __forceinline__ void ldsm4(uint32_t* r, uint32_t addr) {
    asm volatile("ldmatrix.sync.aligned.m8n8.x4.shared.b16 {%0,%1,%2,%3}, [%4];"
                 : "=r"(r[0]), "=r"(r[1]), "=r"(r[2]), "=r"(r[3]) : "r"(addr));
}
__device__ __forceinline__ void mma16816(float* d, const uint32_t* a, uint32_t b0, uint32_t b1) {
    asm volatile(
        "mma.sync.aligned.m16n8k16.row.col.f32.bf16.bf16.f32 "
        "{%0,%1,%2,%3}, {%4,%5,%6,%7}, {%8,%9}, {%0,%1,%2,%3};"
        : "+f"(d[0]), "+f"(d[1]), "+f"(d[2]), "+f"(d[3])
        : "r"(a[0]), "r"(a[1]), "r"(a[2]), "r"(a[3]), "r"(b0), "r"(b1));
}
// SW128-swizzled smem offset for (row, 16B-chunk c) with 128B rows
__device__ __forceinline__ uint32_t swz(int row, int c) {
    return (uint32_t)(row * 128 + ((c ^ (row & 7)) << 4));
}

// ---------------------------------------------------------------------------
// Kernel: W^T bf16 (tiny, independent)
// ---------------------------------------------------------------------------
__global__ void wt_kernel(const float* __restrict__ w) {
    __shared__ float ts[32][33];
    int k0 = blockIdx.x * 32, n0 = blockIdx.y * 32;
    int t = threadIdx.x;
    int a = t >> 5, b = t & 31;
    #pragma unroll
    for (int i = 0; i < 4; ++i)
        ts[a + 8 * i][b] = w[(size_t)(k0 + a + 8 * i) * DOUT + n0 + b];
    __syncthreads();
    #pragma unroll
    for (int i = 0; i < 4; ++i)
        g_WT[(size_t)(n0 + a + 8 * i) * NA + k0 + b] = __float2bfloat16(ts[b][a + 8 * i]);
}

// ---------------------------------------------------------------------------
// Kernel: colsum partials + A+I copy-out (fp32) + bf16(A+I) production.
// ---------------------------------------------------------------------------
__global__ void colsum_fused(const float* __restrict__ in, float* __restrict__ out) {
    int col = (blockIdx.x * 256 + threadIdx.x) * 4;
    int r0  = blockIdx.y * 128;
    const float* p = in + (size_t)r0 * PITCH + ACOL0 + col;
    float*       q = out + (size_t)r0 * OPITCH + DOUT + col;
    __nv_bfloat16* ab = g_Ab + (size_t)r0 * NSMP + col;
    float4 s = make_float4(0.f, 0.f, 0.f, 0.f);
    #pragma unroll 4
    for (int r = 0; r < 128; ++r) {
        float4 v = *(const float4*)p;
        s.x += v.x; s.y += v.y; s.z += v.z; s.w += v.w;   // raw A sums (pre-identity)
        int d = (r0 + r) - col;
        if ((unsigned)d < 4u) ((float*)&v)[d] += 1.f;     // +I
        __stcs((float4*)q, v);                            // fp32 A+I -> out[:,256:]
        __nv_bfloat162 h0 = __floats2bfloat162_rn(v.x, v.y);
        __nv_bfloat162 h1 = __floats2bfloat162_rn(v.z, v.w);
        __stcs((uint2*)ab, make_uint2(*(uint32_t*)&h0, *(uint32_t*)&h1));
        p += PITCH; q += OPITCH; ab += NSMP;
    }
    *(float4*)(g_part + blockIdx.y * NSMP + col) = s;
}

__global__ void finalize_d() {
    int col = blockIdx.x * 256 + threadIdx.x;
    float s = 1.0f;
    #pragma unroll
    for (int i = 0; i < 64; ++i) s += g_part[i * NSMP + col];
    g_dinv[col] = rsqrtf(s);
}

// ---------------------------------------------------------------------------
// support (mma.sync): S_T[n][j] = bf16( dinv[j] * (X @ W)[j,n] )  (R11 form)
// ---------------------------------------------------------------------------
#define SP_A0 0
#define SP_B0 8192
#define SP_A1 40960
#define SP_B1 49152
#define SP_TOTAL 81920
#define ST_PITCH 144

__device__ __forceinline__ void sp_load(const float* in, char* smem, int buf, int k0,
                                        int tid, int m0) {
    uint32_t bs = s2u(smem + (buf ? SP_B1 : SP_B0));
    const char* gB = (const char*)g_WT + (size_t)k0 * 2;
    #pragma unroll
    for (int c = 0; c < 8; ++c) {
        int chunk = tid + c * 256;
        int row = chunk >> 3;
        int seg = chunk & 7;
        cp_async16(bs + swz(row, seg), gB + (size_t)row * (NA * 2) + seg * 16);
    }
    cp_commit();
    char* As = smem + (buf ? SP_A1 : SP_A0);
    int f = tid & 15, r0 = tid >> 4;
    #pragma unroll
    for (int i = 0; i < 4; ++i) {
        int row = r0 + 16 * i;
        float4 v = *(const float4*)(in + (size_t)(m0 + row) * PITCH + k0 + f * 4);
        __nv_bfloat162 h0 = __floats2bfloat162_rn(v.x, v.y);
        __nv_bfloat162 h1 = __floats2bfloat162_rn(v.z, v.w);
        *(uint2*)(As + swz(row, f >> 1) + (f & 1) * 8) =
            make_uint2(*(uint32_t*)&h0, *(uint32_t*)&h1);
    }
}

__global__ void __launch_bounds__(256, 1) support_mma(const float* __restrict__ in) {
    extern __shared__ char smem[];
    int tid = threadIdx.x;
    int wid = tid >> 5, lane = tid & 31;
    int m0 = blockIdx.x * 64;
    int warp_m = (wid & 1) * 32;
    int warp_n = (wid >> 1) * 64;

    int rowA[2], rowB[4];
    #pragma unroll
    for (int mi = 0; mi < 2; ++mi) rowA[mi] = warp_m + mi * 16 + (lane & 15);
    int hiA = lane >> 4;
    #pragma unroll
    for (int nb = 0; nb < 4; ++nb)
        rowB[nb] = warp_n + nb * 16 + ((lane >> 4) << 3) + (lane & 7);
    int hiB = (lane >> 3) & 1;

    float acc[2][8][4] = {};

    sp_load(in, smem, 0, 0, tid, m0);
    for (int it = 0; it < NA / 64; ++it) {
        int buf = it & 1;
        if (it + 1 < NA / 64) { sp_load(in, smem, buf ^ 1, (it + 1) * 64, tid, m0); cp_wait<1>(); }
        else cp_wait<0>();
        __syncthreads();
        uint32_t As = s2u(smem + (buf ? SP_A1 : SP_A0));
        uint32_t Bs = s2u(smem + (buf ? SP_B1 : SP_B0));
        #pragma unroll
        for (int kk = 0; kk < 4; ++kk) {
            uint32_t a[2][4];
            #pragma unroll
            for (int mi = 0; mi < 2; ++mi)
                ldsm4(a[mi], As + swz(rowA[mi], kk * 2 + hiA));
            #pragma unroll
            for (int nb = 0; nb < 4; ++nb) {
                uint32_t b[4];
                ldsm4(b, Bs + swz(rowB[nb], kk * 2 + hiB));
                mma16816(acc[0][2 * nb],     a[0], b[0], b[1]);
                mma16816(acc[0][2 * nb + 1], a[0], b[2], b[3]);
                mma16816(acc[1][2 * nb],     a[1], b[0], b[1]);
                mma16816(acc[1][2 * nb + 1], a[1], b[2], b[3]);
            }
        }
        __syncthreads();
    }

    int qr = lane >> 2, qc = (lane & 3) * 2;
    #pragma unroll
    for (int mi = 0; mi < 2; ++mi) {
        int j0 = warp_m + mi * 16 + qr;
        float dv0 = g_dinv[m0 + j0];
        float dv1 = g_dinv[m0 + j0 + 8];
        #pragma unroll
        for (int n8 = 0; n8 < 8; ++n8) {
            int n = warp_n + n8 * 8 + qc;
            *(__nv_bfloat16*)(smem + n * ST_PITCH + j0 * 2)             = __float2bfloat16(dv0 * acc[mi][n8][0]);
            *(__nv_bfloat16*)(smem + (n + 1) * ST_PITCH + j0 * 2)       = __float2bfloat16(dv0 * acc[mi][n8][1]);
            *(__nv_bfloat16*)(smem + n * ST_PITCH + (j0 + 8) * 2)       = __float2bfloat16(dv1 * acc[mi][n8][2]);
            *(__nv_bfloat16*)(smem + (n + 1) * ST_PITCH + (j0 + 8) * 2) = __float2bfloat16(dv1 * acc[mi][n8][3]);
        }
    }
    __syncthreads();
    #pragma unroll
    for (int c = 0; c < 8; ++c) {
        int chunk = tid + c * 256;
        int n = chunk >> 3;
        int seg = chunk & 7;
        uint4 v = *(const uint4*)(smem + n * ST_PITCH + seg * 16);
        *(uint4*)((char*)g_supT + ((size_t)n * NSMP + m0) * 2 + seg * 16) = v;
    }
}

// ---------------------------------------------------------------------------
// main (K-split x4): accP[z][:, :256] = bf16(A+I)[:, kz] @ S[kz, :]
// CTA 64x128 (R11 winner shape), 4 warps (warp 32x64), 3-stage ring,
// grid (128 m, 2 n, 4 kz) = 1024 CTAs -> ~3 CTAs/SM.
// ---------------------------------------------------------------------------
#define MG7_STRIDE 24576   // per-stage: B(16KB) + A(8KB)
#define MG7_AOFF   16384
#define MG7_TOTAL  73728   // 3 stages
#define KSPLIT     4
#define NIT2       (NSMP / 64 / KSPLIT)   // 32

__device__ __forceinline__ void mg9_load(char* smem, int stage, int k0, int tid,
                                         int m0, int n0) {
    uint32_t bs = s2u(smem + stage * MG7_STRIDE);
    const char* gB = (const char*)g_supT + (size_t)n0 * (NSMP * 2) + (size_t)k0 * 2;
    #pragma unroll
    for (int c = 0; c < 8; ++c) {
        int chunk = tid + c * 128;
        int row = chunk >> 3;
        int seg = chunk & 7;
        cp_async16(bs + swz(row, seg), gB + (size_t)row * (NSMP * 2) + seg * 16);
    }
    uint32_t as_ = s2u(smem + stage * MG7_STRIDE + MG7_AOFF);
    const char* gA = (const char*)g_Ab + (size_t)m0 * (NSMP * 2) + (size_t)k0 * 2;
    #pragma unroll
    for (int c = 0; c < 4; ++c) {
        int chunk = tid + c * 128;
        int row = chunk >> 3;
        int seg = chunk & 7;
        cp_async16(as_ + swz(row, seg), gA + (size_t)row * (NSMP * 2) + seg * 16);
    }
    cp_commit();
}

__global__ void __launch_bounds__(128, 3) main_gemm9(void) {
    extern __shared__ char smem[];
    int tid = threadIdx.x;
    int wid = tid >> 5, lane = tid & 31;
    int m0 = blockIdx.x * 64;
    int n0 = blockIdx.y * 128;
    int kz = blockIdx.z;
    int kbase = kz * (NSMP / KSPLIT);
    int warp_m = (wid & 1) * 32;
    int warp_n = (wid >> 1) * 64;

    int rowA[2], rowB[4];
    #pragma unroll
    for (int mi = 0; mi < 2; ++mi) rowA[mi] = warp_m + mi * 16 + (lane & 15);
    int hiA = lane >> 4;
    #pragma unroll
    for (int nb = 0; nb < 4; ++nb)
        rowB[nb] = warp_n + nb * 16 + ((lane >> 4) << 3) + (lane & 7);
    int hiB = (lane >> 3) & 1;

    float acc[2][8][4] = {};

    mg9_load(smem, 0, kbase, tid, m0, n0);
    mg9_load(smem, 1, kbase + 64, tid, m0, n0);

    for (int it = 0; it < NIT2; ++it) {
        int stage = it % 3;
        if (it + 1 < NIT2) cp_wait<1>(); else cp_wait<0>();
        __syncthreads();
        if (it + 2 < NIT2) mg9_load(smem, (it + 2) % 3, kbase + (it + 2) * 64, tid, m0, n0);

        uint32_t Af = s2u(smem + stage * MG7_STRIDE + MG7_AOFF);
        uint32_t Bs = s2u(smem + stage * MG7_STRIDE);
        #pragma unroll
        for (int kk = 0; kk < 4; ++kk) {
            uint32_t a[2][4];
            #pragma unroll
            for (int mi = 0; mi < 2; ++mi)
                ldsm4(a[mi], Af + swz(rowA[mi], kk * 2 + hiA));
            #pragma unroll
            for (int nb = 0; nb < 4; ++nb) {
                uint32_t b[4];
                ldsm4(b, Bs + swz(rowB[nb], kk * 2 + hiB));
                mma16816(acc[0][2 * nb],     a[0], b[0], b[1]);
                mma16816(acc[0][2 * nb + 1], a[0], b[2], b[3]);
                mma16816(acc[1][2 * nb],     a[1], b[0], b[1]);
                mma16816(acc[1][2 * nb + 1], a[1], b[2], b[3]);
            }
        }
    }

    // epilogue: UNSCALED partials -> g_accP[kz]
    float* accb = g_accP[kz];
    int qr = lane >> 2, qc = (lane & 3) * 2;
    #pragma unroll
    for (int mi = 0; mi < 2; ++mi) {
        int r0g = m0 + warp_m + mi * 16 + qr;
        float* o0 = accb + (size_t)r0g * DOUT + n0;
        float* o1 = o0 + (size_t)8 * DOUT;
        #pragma unroll
        for (int n8 = 0; n8 < 8; ++n8) {
            int col = warp_n + n8 * 8 + qc;
            o0[col]     = acc[mi][n8][0];
            o0[col + 1] = acc[mi][n8][1];
            o1[col]     = acc[mi][n8][2];
            o1[col + 1] = acc[mi][n8][3];
        }
    }
}

// ---------------------------------------------------------------------------
// reduce_out: out[:, :256] = dinv[row] * sum_z accP[z]
// ---------------------------------------------------------------------------
__global__ void reduce_out(float* __restrict__ out) {
    int idx = blockIdx.x * 256 + threadIdx.x;   // 0 .. 8192*64-1 (float4 units)
    int row = idx >> 6;
    int c4  = (idx & 63) * 4;
    size_t off = (size_t)row * DOUT + c4;
    float4 a0 = *(const float4*)(g_accP[0] + off);
    float4 a1 = *(const float4*)(g_accP[1] + off);
    float4 a2 = *(const float4*)(g_accP[2] + off);
    float4 a3 = *(const float4*)(g_accP[3] + off);
    float dv = g_dinv[row];
    float4 r;
    r.x = dv * ((a0.x + a1.x) + (a2.x + a3.x));
    r.y = dv * ((a0.y + a1.y) + (a2.y + a3.y));
    r.z = dv * ((a0.z + a1.z) + (a2.z + a3.z));
    r.w = dv * ((a0.w + a1.w) + (a2.w + a3.w));
    *(float4*)(out + (size_t)row * OPITCH + c4) = r;
}

// ---------------------------------------------------------------------------
extern "C" void kernel_launch(void* const* d_in, const int* in_sizes, int n_in,
                              void* d_out, int out_size) {
    const float* in = (const float*)d_in[0];
    const float* w  = (const float*)d_in[1];
    float* out = (float*)d_out;

    cudaFuncSetAttribute(support_mma, cudaFuncAttributeMaxDynamicSharedMemorySize, SP_TOTAL);
    cudaFuncSetAttribute(main_gemm9,  cudaFuncAttributeMaxDynamicSharedMemorySize, MG7_TOTAL);

    wt_kernel   <<<dim3(16, 8), 256>>>(w);
    colsum_fused<<<dim3(8, 64), 256>>>(in, out);
    finalize_d  <<<32, 256>>>();
    support_mma <<<128, 256, SP_TOTAL>>>(in);
    main_gemm9  <<<dim3(128, 2, 4), 128, MG7_TOTAL>>>();
    reduce_out  <<<2048, 256>>>(out);
}

// round 15
// speedup vs baseline: 1.2470x; 1.0746x over previous
#include <cuda_runtime.h>
#include <cuda_bf16.h>
#include <cstdint>

#define NSMP   8192
#define NA     512
#define DOUT   256
#define PITCH  8712   // input row length
#define ACOL0  512    // A starts at input col 512
#define OPITCH 8448   // output row length

// Scratch (static device globals — no runtime allocation)
__device__ float g_part[64 * NSMP];
__device__ float g_dinv[NSMP];
__device__ __align__(16) __nv_bfloat16 g_supT[(size_t)DOUT * NSMP]; // S_T[n][j]
__device__ __align__(16) __nv_bfloat16 g_WT[(size_t)DOUT * NA];     // W^T[n][k] bf16
__device__ __align__(16) __nv_bfloat16 g_Ab[(size_t)NSMP * NSMP];   // bf16(A+I)

// ---------------------------------------------------------------------------
// PTX helpers (base-target-safe)
// ---------------------------------------------------------------------------
__device__ __forceinline__ uint32_t s2u(const void* p) {
    return (uint32_t)__cvta_generic_to_shared(p);
}
__device__ __forceinline__ void cp_async16(uint32_t s, const void* g) {
    asm volatile("cp.async.cg.shared.global [%0], [%1], 16;" :: "r"(s), "l"(g) : "memory");
}
__device__ __forceinline__ void cp_commit() {
    asm volatile("cp.async.commit_group;" ::: "memory");
}
template <int N>
__device__ __forceinline__ void cp_wait() {
    asm volatile("cp.async.wait_group %0;" :: "n"(N) : "memory");
}
__device__ __forceinline__ void ldsm4(uint32_t* r, uint32_t addr) {
    asm volatile("ldmatrix.sync.aligned.m8n8.x4.shared.b16 {%0,%1,%2,%3}, [%4];"
                 : "=r"(r[0]), "=r"(r[1]), "=r"(r[2]), "=r"(r[3]) : "r"(addr));
}
__device__ __forceinline__ void mma16816(float* d, const uint32_t* a, uint32_t b0, uint32_t b1) {
    asm volatile(
        "mma.sync.aligned.m16n8k16.row.col.f32.bf16.bf16.f32 "
        "{%0,%1,%2,%3}, {%4,%5,%6,%7}, {%8,%9}, {%0,%1,%2,%3};"
        : "+f"(d[0]), "+f"(d[1]), "+f"(d[2]), "+f"(d[3])
        : "r"(a[0]), "r"(a[1]), "r"(a[2]), "r"(a[3]), "r"(b0), "r"(b1));
}
// SW128-swizzled smem offset for (row, 16B-chunk c) with 128B rows
__device__ __forceinline__ uint32_t swz(int row, int c) {
    return (uint32_t)(row * 128 + ((c ^ (row & 7)) << 4));
}

// ---------------------------------------------------------------------------
// pre_kernel: blocks 0..127   -> W^T bf16 role (tiny)
//             blocks 128..639 -> colsum partials + A+I fp32 copy + bf16(A+I)
// ---------------------------------------------------------------------------
__device__ void wt_role(const float* __restrict__ w, int b) {
    __shared__ float ts[32][33];
    int k0 = (b & 15) * 32, n0 = (b >> 4) * 32;
    int t = threadIdx.x;
    int a = t >> 5, c = t & 31;
    #pragma unroll
    for (int i = 0; i < 4; ++i)
        ts[a + 8 * i][c] = w[(size_t)(k0 + a + 8 * i) * DOUT + n0 + c];
    __syncthreads();
    #pragma unroll
    for (int i = 0; i < 4; ++i)
        g_WT[(size_t)(n0 + a + 8 * i) * NA + k0 + c] = __float2bfloat16(ts[c][a + 8 * i]);
}

__device__ void colsum_role(const float* __restrict__ in, float* __restrict__ out, int b) {
    int bx = b & 7, by = b >> 3;
    int col = (bx * 256 + threadIdx.x) * 4;
    int r0  = by * 128;
    const float* p = in + (size_t)r0 * PITCH + ACOL0 + col;
    float*       q = out + (size_t)r0 * OPITCH + DOUT + col;
    __nv_bfloat16* ab = g_Ab + (size_t)r0 * NSMP + col;
    float4 s = make_float4(0.f, 0.f, 0.f, 0.f);
    #pragma unroll 4
    for (int r = 0; r < 128; ++r) {
        float4 v = *(const float4*)p;
        s.x += v.x; s.y += v.y; s.z += v.z; s.w += v.w;   // raw A sums (pre-identity)
        int d = (r0 + r) - col;
        if ((unsigned)d < 4u) ((float*)&v)[d] += 1.f;     // +I
        __stcs((float4*)q, v);                            // fp32 A+I -> out[:,256:]
        __nv_bfloat162 h0 = __floats2bfloat162_rn(v.x, v.y);
        __nv_bfloat162 h1 = __floats2bfloat162_rn(v.z, v.w);
        __stcs((uint2*)ab, make_uint2(*(uint32_t*)&h0, *(uint32_t*)&h1));
        p += PITCH; q += OPITCH; ab += NSMP;
    }
    *(float4*)(g_part + by * NSMP + col) = s;
}

__global__ void pre_kernel(const float* __restrict__ in, const float* __restrict__ w,
                           float* __restrict__ out) {
    if (blockIdx.x < 128) wt_role(w, blockIdx.x);
    else                  colsum_role(in, out, blockIdx.x - 128);
}

// ---------------------------------------------------------------------------
// support (mma.sync): S_T[n][j] = bf16( dinv[j] * (X @ W)[j,n] )
// Computes dinv for its own 64 rows in the prologue (replaces finalize_d).
// ---------------------------------------------------------------------------
#define SP_A0 0
#define SP_B0 8192
#define SP_A1 40960
#define SP_B1 49152
#define SP_TOTAL 81920
#define ST_PITCH 144

__device__ __forceinline__ void sp_load(const float* in, char* smem, int buf, int k0,
                                        int tid, int m0) {
    uint32_t bs = s2u(smem + (buf ? SP_B1 : SP_B0));
    const char* gB = (const char*)g_WT + (size_t)k0 * 2;
    #pragma unroll
    for (int c = 0; c < 8; ++c) {
        int chunk = tid + c * 256;
        int row = chunk >> 3;
        int seg = chunk & 7;
        cp_async16(bs + swz(row, seg), gB + (size_t)row * (NA * 2) + seg * 16);
    }
    cp_commit();
    char* As = smem + (buf ? SP_A1 : SP_A0);
    int f = tid & 15, r0 = tid >> 4;
    #pragma unroll
    for (int i = 0; i < 4; ++i) {
        int row = r0 + 16 * i;
        float4 v = *(const float4*)(in + (size_t)(m0 + row) * PITCH + k0 + f * 4);
        __nv_bfloat162 h0 = __floats2bfloat162_rn(v.x, v.y);
        __nv_bfloat162 h1 = __floats2bfloat162_rn(v.z, v.w);
        *(uint2*)(As + swz(row, f >> 1) + (f & 1) * 8) =
            make_uint2(*(uint32_t*)&h0, *(uint32_t*)&h1);
    }
}

__global__ void __launch_bounds__(256, 1) support_mma(const float* __restrict__ in) {
    extern __shared__ char smem[];
    __shared__ float sdv[64];
    int tid = threadIdx.x;
    int wid = tid >> 5, lane = tid & 31;
    int m0 = blockIdx.x * 64;
    int warp_m = (wid & 1) * 32;
    int warp_n = (wid >> 1) * 64;

    // dinv for this CTA's 64 rows (was finalize_d)
    if (tid < 64) {
        float s = 1.0f;
        #pragma unroll
        for (int i = 0; i < 64; ++i) s += g_part[i * NSMP + m0 + tid];
        float dv = rsqrtf(s);
        sdv[tid] = dv;
        g_dinv[m0 + tid] = dv;   // main_gemm reads this later
    }

    int rowA[2], rowB[4];
    #pragma unroll
    for (int mi = 0; mi < 2; ++mi) rowA[mi] = warp_m + mi * 16 + (lane & 15);
    int hiA = lane >> 4;
    #pragma unroll
    for (int nb = 0; nb < 4; ++nb)
        rowB[nb] = warp_n + nb * 16 + ((lane >> 4) << 3) + (lane & 7);
    int hiB = (lane >> 3) & 1;

    float acc[2][8][4] = {};

    sp_load(in, smem, 0, 0, tid, m0);
    for (int it = 0; it < NA / 64; ++it) {
        int buf = it & 1;
        if (it + 1 < NA / 64) { sp_load(in, smem, buf ^ 1, (it + 1) * 64, tid, m0); cp_wait<1>(); }
        else cp_wait<0>();
        __syncthreads();
        uint32_t As = s2u(smem + (buf ? SP_A1 : SP_A0));
        uint32_t Bs = s2u(smem + (buf ? SP_B1 : SP_B0));
        #pragma unroll
        for (int kk = 0; kk < 4; ++kk) {
            uint32_t a[2][4];
            #pragma unroll
            for (int mi = 0; mi < 2; ++mi)
                ldsm4(a[mi], As + swz(rowA[mi], kk * 2 + hiA));
            #pragma unroll
            for (int nb = 0; nb < 4; ++nb) {
                uint32_t b[4];
                ldsm4(b, Bs + swz(rowB[nb], kk * 2 + hiB));
                mma16816(acc[0][2 * nb],     a[0], b[0], b[1]);
                mma16816(acc[0][2 * nb + 1], a[0], b[2], b[3]);
                mma16816(acc[1][2 * nb],     a[1], b[0], b[1]);
                mma16816(acc[1][2 * nb + 1], a[1], b[2], b[3]);
            }
        }
        __syncthreads();
    }

    int qr = lane >> 2, qc = (lane & 3) * 2;
    #pragma unroll
    for (int mi = 0; mi < 2; ++mi) {
        int j0 = warp_m + mi * 16 + qr;
        float dv0 = sdv[j0];
        float dv1 = sdv[j0 + 8];
        #pragma unroll
        for (int n8 = 0; n8 < 8; ++n8) {
            int n = warp_n + n8 * 8 + qc;
            *(__nv_bfloat16*)(smem + n * ST_PITCH + j0 * 2)             = __float2bfloat16(dv0 * acc[mi][n8][0]);
            *(__nv_bfloat16*)(smem + (n + 1) * ST_PITCH + j0 * 2)       = __float2bfloat16(dv0 * acc[mi][n8][1]);
            *(__nv_bfloat16*)(smem + n * ST_PITCH + (j0 + 8) * 2)       = __float2bfloat16(dv1 * acc[mi][n8][2]);
            *(__nv_bfloat16*)(smem + (n + 1) * ST_PITCH + (j0 + 8) * 2) = __float2bfloat16(dv1 * acc[mi][n8][3]);
        }
    }
    __syncthreads();
    #pragma unroll
    for (int c = 0; c < 8; ++c) {
        int chunk = tid + c * 256;
        int n = chunk >> 3;
        int seg = chunk & 7;
        uint4 v = *(const uint4*)(smem + n * ST_PITCH + seg * 16);
        *(uint4*)((char*)g_supT + ((size_t)n * NSMP + m0) * 2 + seg * 16) = v;
    }
}

// ---------------------------------------------------------------------------
// main (pure bf16 GEMM): out[:, :256] = diag(dinv) * bf16(A+I) @ S
// 128-thread CTAs (4 warps, warp tile 32x64), CTA 64x128, grid (128, 2),
// 3-stage cp.async ring (72KB smem). (R11 winner, unchanged)
// ---------------------------------------------------------------------------
#define MG7_STRIDE 24576   // per-stage: B(16KB) + A(8KB)
#define MG7_AOFF   16384
#define MG7_TOTAL  73728   // 3 stages
#define NIT        (NSMP / 64)

__device__ __forceinline__ void mg7_load(char* smem, int stage, int k0, int tid,
                                         int m0, int n0) {
    uint32_t bs = s2u(smem + stage * MG7_STRIDE);
    const char* gB = (const char*)g_supT + (size_t)n0 * (NSMP * 2) + (size_t)k0 * 2;
    #pragma unroll
    for (int c = 0; c < 8; ++c) {
        int chunk = tid + c * 128;
        int row = chunk >> 3;
        int seg = chunk & 7;
        cp_async16(bs + swz(row, seg), gB + (size_t)row * (NSMP * 2) + seg * 16);
    }
    uint32_t as_ = s2u(smem + stage * MG7_STRIDE + MG7_AOFF);
    const char* gA = (const char*)g_Ab + (size_t)m0 * (NSMP * 2) + (size_t)k0 * 2;
    #pragma unroll
    for (int c = 0; c < 4; ++c) {
        int chunk = tid + c * 128;
        int row = chunk >> 3;
        int seg = chunk & 7;
        cp_async16(as_ + swz(row, seg), gA + (size_t)row * (NSMP * 2) + seg * 16);
    }
    cp_commit();
}

__global__ void __launch_bounds__(128, 3) main_gemm7(float* __restrict__ out) {
    extern __shared__ char smem[];
    int tid = threadIdx.x;
    int wid = tid >> 5, lane = tid & 31;
    int m0 = blockIdx.x * 64;
    int n0 = blockIdx.y * 128;
    int warp_m = (wid & 1) * 32;
    int warp_n = (wid >> 1) * 64;

    int rowA[2], rowB[4];
    #pragma unroll
    for (int mi = 0; mi < 2; ++mi) rowA[mi] = warp_m + mi * 16 + (lane & 15);
    int hiA = lane >> 4;
    #pragma unroll
    for (int nb = 0; nb < 4; ++nb)
        rowB[nb] = warp_n + nb * 16 + ((lane >> 4) << 3) + (lane & 7);
    int hiB = (lane >> 3) & 1;

    float acc[2][8][4] = {};

    mg7_load(smem, 0, 0, tid, m0, n0);
    mg7_load(smem, 1, 64, tid, m0, n0);

    for (int it = 0; it < NIT; ++it) {
        int stage = it % 3;
        if (it + 1 < NIT) cp_wait<1>(); else cp_wait<0>();
        __syncthreads();
        if (it + 2 < NIT) mg7_load(smem, (it + 2) % 3, (it + 2) * 64, tid, m0, n0);

        uint32_t Af = s2u(smem + stage * MG7_STRIDE + MG7_AOFF);
        uint32_t Bs = s2u(smem + stage * MG7_STRIDE);
        #pragma unroll
        for (int kk = 0; kk < 4; ++kk) {
            uint32_t a[2][4];
            #pragma unroll
            for (int mi = 0; mi < 2; ++mi)
                ldsm4(a[mi], Af + swz(rowA[mi], kk * 2 + hiA));
            #pragma unroll
            for (int nb = 0; nb < 4; ++nb) {
                uint32_t b[4];
                ldsm4(b, Bs + swz(rowB[nb], kk * 2 + hiB));
                mma16816(acc[0][2 * nb],     a[0], b[0], b[1]);
                mma16816(acc[0][2 * nb + 1], a[0], b[2], b[3]);
                mma16816(acc[1][2 * nb],     a[1], b[0], b[1]);
                mma16816(acc[1][2 * nb + 1], a[1], b[2], b[3]);
            }
        }
    }

    // epilogue: scale by dinv[row], store out[:, n0 + warp_n ...]
    int qr = lane >> 2, qc = (lane & 3) * 2;
    #pragma unroll
    for (int mi = 0; mi < 2; ++mi) {
        int r0g = m0 + warp_m + mi * 16 + qr;
        float dv0 = g_dinv[r0g];
        float dv1 = g_dinv[r0g + 8];
        float* o0 = out + (size_t)r0g * OPITCH + n0;
        float* o1 = o0 + (size_t)8 * OPITCH;
        #pragma unroll
        for (int n8 = 0; n8 < 8; ++n8) {
            int col = warp_n + n8 * 8 + qc;
            o0[col]     = dv0 * acc[mi][n8][0];
            o0[col + 1] = dv0 * acc[mi][n8][1];
            o1[col]     = dv1 * acc[mi][n8][2];
            o1[col + 1] = dv1 * acc[mi][n8][3];
        }
    }
}

// ---------------------------------------------------------------------------
extern "C" void kernel_launch(void* const* d_in, const int* in_sizes, int n_in,
                              void* d_out, int out_size) {
    const float* in = (const float*)d_in[0];
    const float* w  = (const float*)d_in[1];
    float* out = (float*)d_out;

    cudaFuncSetAttribute(support_mma, cudaFuncAttributeMaxDynamicSharedMemorySize, SP_TOTAL);
    cudaFuncSetAttribute(main_gemm7,  cudaFuncAttributeMaxDynamicSharedMemorySize, MG7_TOTAL);

    pre_kernel <<<640, 256>>>(in, w, out);
    support_mma<<<128, 256, SP_TOTAL>>>(in);
    main_gemm7 <<<dim3(128, 2), 128, MG7_TOTAL>>>(out);
}